// round 8
// baseline (speedup 1.0000x reference)
#include <cuda_runtime.h>
#include <math.h>

#define B_ 4
#define N_ 1024
#define H_ 8
#define D_ 256
#define L_ 4
#define DK_ 32
#define NSP_ 512
#define BND (B_*N_*D_)   // 1048576
#define ND  (N_*D_)      // 262144

typedef unsigned long long u64;

// ---------------- f32x2 packed-math helpers (sm_100+) ----------------
__device__ __forceinline__ u64 pk2(float x, float y) {
    u64 r; asm("mov.b64 %0, {%1, %2};" : "=l"(r) : "f"(x), "f"(y)); return r;
}
__device__ __forceinline__ float2 upk2(u64 a) {
    float2 f; asm("mov.b64 {%0, %1}, %2;" : "=f"(f.x), "=f"(f.y) : "l"(a)); return f;
}
__device__ __forceinline__ u64 fma2_(u64 a, u64 b, u64 c) {
    u64 d; asm("fma.rn.f32x2 %0, %1, %2, %3;" : "=l"(d) : "l"(a), "l"(b), "l"(c)); return d;
}
__device__ __forceinline__ u64 mul2_(u64 a, u64 b) {
    u64 d; asm("mul.rn.f32x2 %0, %1, %2;" : "=l"(d) : "l"(a), "l"(b)); return d;
}

// ---------------- scratch (static device globals; no allocation) ----------------
__device__ float g_h [BND];
__device__ float g_q [BND];
__device__ float g_k [BND];
__device__ float g_v [BND];
__device__ float g_t1[BND];
__device__ float g_t2[BND];
__device__ float g_node[ND];
__device__ float g_bias[H_ * N_ * N_];   // 32MB precomputed bias [H][N][N]

// ---------------- prologue: node-level embeddings ----------------
__global__ void node_vec_kernel(const float* __restrict__ svd_emb,
                                const float* __restrict__ W_svd,
                                const float* __restrict__ b_svd,
                                const float* __restrict__ in_deg_emb,
                                const float* __restrict__ out_deg_emb,
                                const int*   __restrict__ in_degrees,
                                const int*   __restrict__ out_degrees,
                                float* __restrict__ nodevec)
{
    int n = blockIdx.x;
    int d = threadIdx.x;           // 256 threads
    __shared__ float pos[32];
    if (d < 32) {
        float v = svd_emb[n * 32 + d];
        pos[d] = (d < 16) ? v : -v;
    }
    __syncthreads();
    int in_i  = in_degrees[n];
    int out_i = out_degrees[n];
    float acc = b_svd[d] + in_deg_emb[in_i * D_ + d] + out_deg_emb[out_i * D_ + d];
#pragma unroll
    for (int k = 0; k < 32; k++)
        acc += pos[k] * W_svd[k * D_ + d];
    nodevec[n * D_ + d] = acc;
}

__global__ void add_node_kernel(const float* __restrict__ x,
                                const float* __restrict__ nodevec,
                                float* __restrict__ h)
{
    int i = blockIdx.x * blockDim.x + threadIdx.x;
    h[i] = x[i] + nodevec[i & (ND - 1)];
}

// ---------------- precompute attention bias ----------------
__global__ void bias_kernel(const int* __restrict__ spatial_pos,
                            const float* __restrict__ spatial_emb,
                            float* __restrict__ bias)
{
    int i = blockIdx.x * 256 + threadIdx.x;     // over N*N = 1M
    int s = spatial_pos[i];
#pragma unroll
    for (int h = 0; h < H_; h++)
        bias[(size_t)h * (N_ * N_) + i] = spatial_emb[s * H_ + h];
}

// ---------------- GEMM: 64x64 tile, 256 threads, 4x4 microtile, dup-B f32x2 ----------------
#define BM 64
#define BN 64
#define BK 16
__device__ __forceinline__ void gemm_body(const float* __restrict__ A,
                                          const float* __restrict__ W,
                                          const float* __restrict__ bias,
                                          const float* __restrict__ res,
                                          float* __restrict__ out,
                                          int relu, int bm, int bn)
{
    __shared__ __align__(16) float As[BK][BM + 4];   // [16][68] 4.3KB
    __shared__ __align__(16) u64   Bs2[BK][BN];      // duplicated pairs, 8KB

    int tid = threadIdx.x;            // 256
    int tx = tid & 15;                // n dir: 4 cols
    int ty = tid >> 4;                // m dir: 4 rows (2 f32x2 pairs)

    int ar = tid >> 2;                // A row 0..63
    int ac = (tid & 3) * 4;           // A k-chunk
    int br = tid >> 4;                // B k-row 0..15
    int bc = (tid & 15) * 4;          // B n-chunk

    const float* Ap = A + (size_t)(bm + ar) * 256 + ac;
    const float* Wp = W + (size_t)br * 256 + bn + bc;

    float4 a_reg = *reinterpret_cast<const float4*>(Ap);
    float4 b_reg = *reinterpret_cast<const float4*>(Wp);

    u64 acc2[2][4] = {};   // [m-pair][n]

#pragma unroll 1
    for (int k0 = 0; k0 < 256; k0 += BK) {
        As[ac + 0][ar] = a_reg.x; As[ac + 1][ar] = a_reg.y;
        As[ac + 2][ar] = a_reg.z; As[ac + 3][ar] = a_reg.w;
        {
            ulonglong2 p01, p23;
            p01.x = pk2(b_reg.x, b_reg.x); p01.y = pk2(b_reg.y, b_reg.y);
            p23.x = pk2(b_reg.z, b_reg.z); p23.y = pk2(b_reg.w, b_reg.w);
            *reinterpret_cast<ulonglong2*>(&Bs2[br][bc])     = p01;
            *reinterpret_cast<ulonglong2*>(&Bs2[br][bc + 2]) = p23;
        }
        __syncthreads();
        if (k0 + BK < 256) {
            a_reg = *reinterpret_cast<const float4*>(Ap + k0 + BK);
            b_reg = *reinterpret_cast<const float4*>(Wp + (size_t)(k0 + BK) * 256);
        }
#pragma unroll
        for (int kk = 0; kk < BK; kk++) {
            ulonglong2 aa  = *reinterpret_cast<const ulonglong2*>(&As[kk][ty * 4]);
            ulonglong2 b01 = *reinterpret_cast<const ulonglong2*>(&Bs2[kk][tx * 4]);
            ulonglong2 b23 = *reinterpret_cast<const ulonglong2*>(&Bs2[kk][tx * 4 + 2]);
            acc2[0][0] = fma2_(aa.x, b01.x, acc2[0][0]);
            acc2[1][0] = fma2_(aa.y, b01.x, acc2[1][0]);
            acc2[0][1] = fma2_(aa.x, b01.y, acc2[0][1]);
            acc2[1][1] = fma2_(aa.y, b01.y, acc2[1][1]);
            acc2[0][2] = fma2_(aa.x, b23.x, acc2[0][2]);
            acc2[1][2] = fma2_(aa.y, b23.x, acc2[1][2]);
            acc2[0][3] = fma2_(aa.x, b23.y, acc2[0][3]);
            acc2[1][3] = fma2_(aa.y, b23.y, acc2[1][3]);
        }
        __syncthreads();
    }

    int n = bn + tx * 4;
    float4 bb = *reinterpret_cast<const float4*>(bias + n);
#pragma unroll
    for (int mi = 0; mi < 4; mi++) {
        int m = bm + ty * 4 + mi;
        float4 vv;
        {
            float2 t0 = upk2(acc2[mi >> 1][0]);
            float2 t1 = upk2(acc2[mi >> 1][1]);
            float2 t2 = upk2(acc2[mi >> 1][2]);
            float2 t3 = upk2(acc2[mi >> 1][3]);
            if (mi & 1) { vv.x = t0.y; vv.y = t1.y; vv.z = t2.y; vv.w = t3.y; }
            else        { vv.x = t0.x; vv.y = t1.x; vv.z = t2.x; vv.w = t3.x; }
        }
        vv.x += bb.x; vv.y += bb.y; vv.z += bb.z; vv.w += bb.w;
        if (res) {
            float4 rr = *reinterpret_cast<const float4*>(res + (size_t)m * 256 + n);
            vv.x += rr.x; vv.y += rr.y; vv.z += rr.z; vv.w += rr.w;
        }
        if (relu) {
            vv.x = fmaxf(vv.x, 0.f); vv.y = fmaxf(vv.y, 0.f);
            vv.z = fmaxf(vv.z, 0.f); vv.w = fmaxf(vv.w, 0.f);
        }
        *reinterpret_cast<float4*>(out + (size_t)m * 256 + n) = vv;
    }
}

__global__ void __launch_bounds__(256)
gemm256_kernel(const float* __restrict__ A, const float* __restrict__ W,
               const float* __restrict__ bias, const float* __restrict__ res,
               float* __restrict__ out, int relu)
{
    gemm_body(A, W, bias, res, out, relu, blockIdx.x * BM, blockIdx.y * BN);
}

__global__ void __launch_bounds__(256)
qkv_kernel(const float* __restrict__ A,
           const float* __restrict__ Wq, const float* __restrict__ Wk, const float* __restrict__ Wv,
           const float* __restrict__ bq, const float* __restrict__ bk, const float* __restrict__ bv,
           float* __restrict__ q, float* __restrict__ k, float* __restrict__ v)
{
    const float* W; const float* bias; float* out;
    if (blockIdx.z == 0)      { W = Wq; bias = bq; out = q; }
    else if (blockIdx.z == 1) { W = Wk; bias = bk; out = k; }
    else                      { W = Wv; bias = bv; out = v; }
    gemm_body(A, W, bias, nullptr, out, 0, blockIdx.x * BM, blockIdx.y * BN);
}

// ---------------- flash attention: q-tile 64, 64 threads (2 warps), lane = query ----------------
// grid: (N/64, B*H). Warp w owns queries q0 + w*32 + lane. f32x2 math, dual QK chains.
__global__ void __launch_bounds__(64)
attn_kernel(const float* __restrict__ q,
            const float* __restrict__ k,
            const float* __restrict__ v,
            const float* __restrict__ bias,   // [H][N][N]
            float* __restrict__ out)
{
    int bh = blockIdx.y;
    int b  = bh >> 3;
    int h  = bh & 7;
    int q0 = blockIdx.x * 64;

    __shared__ __align__(16) float Ks[32][36];
    __shared__ __align__(16) float Vs[32][36];
    __shared__ float Bt[64][33];

    int tid  = threadIdx.x;
    int w    = tid >> 5;
    int lane = tid & 31;
    int qrow = w * 32 + lane;          // 0..63
    int qi   = q0 + qrow;

    const float scale = 0.1767766952966369f;   // 1/sqrt(32)

    u64 qv2[16], o2[16];
    {
        const float4* qp = reinterpret_cast<const float4*>(
            q + ((size_t)(b * N_ + qi)) * D_ + h * DK_);
#pragma unroll
        for (int d4 = 0; d4 < 8; d4++) {
            float4 t = qp[d4];
            qv2[d4*2+0] = pk2(t.x * scale, t.y * scale);
            qv2[d4*2+1] = pk2(t.z * scale, t.w * scale);
        }
    }
#pragma unroll
    for (int d = 0; d < 16; d++) o2[d] = 0ull;
    float m = -1e30f, l = 0.0f;

    const float* bbase = bias + (size_t)h * (N_ * N_);

    for (int k0 = 0; k0 < N_; k0 += 32) {
        __syncthreads();
        {
            const float* kb = k + ((size_t)(b * N_ + k0)) * D_ + h * DK_;
            const float* vb = v + ((size_t)(b * N_ + k0)) * D_ + h * DK_;
#pragma unroll
            for (int it = 0; it < 4; it++) {
                int i  = tid + it * 64;          // 0..255
                int r  = i >> 3;
                int c4 = (i & 7) * 4;
                float4 kk4 = *reinterpret_cast<const float4*>(kb + (size_t)r * D_ + c4);
                float4 vv4 = *reinterpret_cast<const float4*>(vb + (size_t)r * D_ + c4);
                *reinterpret_cast<float4*>(&Ks[r][c4]) = kk4;
                *reinterpret_cast<float4*>(&Vs[r][c4]) = vv4;
            }
            const float* bt = bbase + (size_t)q0 * N_ + k0;
#pragma unroll
            for (int it = 0; it < 8; it++) {
                int i  = tid + it * 64;          // 0..511
                int r  = i >> 3;
                int c4 = (i & 7) * 4;
                float4 bb = *reinterpret_cast<const float4*>(bt + (size_t)r * N_ + c4);
                Bt[r][c4 + 0] = bb.x; Bt[r][c4 + 1] = bb.y;
                Bt[r][c4 + 2] = bb.z; Bt[r][c4 + 3] = bb.w;
            }
        }
        __syncthreads();

        // scores: dual accumulator chains per key
        float s[32];
#pragma unroll
        for (int kk = 0; kk < 32; kk++) {
            u64 svA = 0ull, svB = 0ull;
            const ulonglong2* kr = reinterpret_cast<const ulonglong2*>(&Ks[kk][0]);
#pragma unroll
            for (int p = 0; p < 8; p++) {
                ulonglong2 kp = kr[p];
                svA = fma2_(qv2[2*p + 0], kp.x, svA);
                svB = fma2_(qv2[2*p + 1], kp.y, svB);
            }
            float2 sa = upk2(svA);
            float2 sb = upk2(svB);
            s[kk] = (sa.x + sa.y) + (sb.x + sb.y) + Bt[qrow][kk];
        }

        float tmax = s[0];
#pragma unroll
        for (int kk = 1; kk < 32; kk++) tmax = fmaxf(tmax, s[kk]);
        float mnew  = fmaxf(m, tmax);
        float alpha = __expf(m - mnew);
        float psum = 0.0f;
#pragma unroll
        for (int kk = 0; kk < 32; kk++) {
            float p = __expf(s[kk] - mnew);
            s[kk] = p;
            psum += p;
        }
        l = l * alpha + psum;
        m = mnew;

        u64 al2 = pk2(alpha, alpha);
#pragma unroll
        for (int d = 0; d < 16; d++) o2[d] = mul2_(o2[d], al2);

#pragma unroll
        for (int kk = 0; kk < 32; kk++) {
            u64 p2 = pk2(s[kk], s[kk]);
            const ulonglong2* vr = reinterpret_cast<const ulonglong2*>(&Vs[kk][0]);
#pragma unroll
            for (int p = 0; p < 8; p++) {
                ulonglong2 vp = vr[p];
                o2[2*p + 0] = fma2_(p2, vp.x, o2[2*p + 0]);
                o2[2*p + 1] = fma2_(p2, vp.y, o2[2*p + 1]);
            }
        }
    }

    float inv = 1.0f / l;
    float* ob = out + ((size_t)(b * N_ + qi)) * D_ + h * DK_;
#pragma unroll
    for (int d4 = 0; d4 < 8; d4++) {
        float2 t0 = upk2(o2[d4*2 + 0]);
        float2 t1 = upk2(o2[d4*2 + 1]);
        float4 t;
        t.x = t0.x * inv; t.y = t0.y * inv;
        t.z = t1.x * inv; t.w = t1.y * inv;
        *reinterpret_cast<float4*>(ob + d4 * 4) = t;
    }
}

// ---------------- LayerNorm over D=256 ----------------
__global__ void __launch_bounds__(256)
ln_kernel(const float* __restrict__ z,
          const float* __restrict__ g,
          const float* __restrict__ bta,
          float* __restrict__ out)
{
    int row = blockIdx.x;
    int t   = threadIdx.x;
    int lane = t & 31, wid = t >> 5;
    __shared__ float red1[8], red2[8];

    float vv = z[(size_t)row * 256 + t];
    float s = vv;
#pragma unroll
    for (int off = 16; off; off >>= 1) s += __shfl_xor_sync(0xffffffffu, s, off);
    if (lane == 0) red1[wid] = s;
    __syncthreads();
    float tot = 0.0f;
#pragma unroll
    for (int i = 0; i < 8; i++) tot += red1[i];
    float mu = tot * (1.0f / 256.0f);

    float d = vv - mu;
    float sq = d * d;
#pragma unroll
    for (int off = 16; off; off >>= 1) sq += __shfl_xor_sync(0xffffffffu, sq, off);
    if (lane == 0) red2[wid] = sq;
    __syncthreads();
    float var = 0.0f;
#pragma unroll
    for (int i = 0; i < 8; i++) var += red2[i];
    var *= (1.0f / 256.0f);

    out[(size_t)row * 256 + t] = d * rsqrtf(var + 1e-6f) * g[t] + bta[t];
}

// ---------------- launch ----------------
extern "C" void kernel_launch(void* const* d_in, const int* in_sizes, int n_in,
                              void* d_out, int out_size)
{
    (void)n_in; (void)out_size;

    const float *x, *svd_emb, *W_svd, *b_svd, *in_deg_emb, *out_deg_emb, *spatial_emb;
    const float *Wq, *Wk, *Wv, *Wa, *W1, *W2;
    const float *bq, *bk, *bv, *ba, *b1, *b2;
    const float *ln1_g, *ln1_b, *ln2_g, *ln2_b;
    const int *in_degrees, *out_degrees, *spatial_pos;

    if (in_sizes[1] == 1024) {
        // setup_inputs dict order
        x           = (const float*)d_in[0];
        in_degrees  = (const int*)  d_in[1];
        out_degrees = (const int*)  d_in[2];
        spatial_pos = (const int*)  d_in[3];
        svd_emb     = (const float*)d_in[4];
        in_deg_emb  = (const float*)d_in[5];
        out_deg_emb = (const float*)d_in[6];
        spatial_emb = (const float*)d_in[7];
        W_svd       = (const float*)d_in[8];
        b_svd       = (const float*)d_in[9];
        Wq = (const float*)d_in[10]; Wk = (const float*)d_in[11];
        Wv = (const float*)d_in[12]; Wa = (const float*)d_in[13];
        W1 = (const float*)d_in[14]; W2 = (const float*)d_in[15];
        bq = (const float*)d_in[16]; bk = (const float*)d_in[17];
        bv = (const float*)d_in[18]; ba = (const float*)d_in[19];
        b1 = (const float*)d_in[20]; b2 = (const float*)d_in[21];
        ln1_b = (const float*)d_in[22]; ln2_b = (const float*)d_in[23];
        ln1_g = (const float*)d_in[24]; ln2_g = (const float*)d_in[25];
    } else {
        // reference() signature order
        x           = (const float*)d_in[0];
        svd_emb     = (const float*)d_in[1];
        W_svd       = (const float*)d_in[2];
        b_svd       = (const float*)d_in[3];
        in_deg_emb  = (const float*)d_in[4];
        out_deg_emb = (const float*)d_in[5];
        spatial_emb = (const float*)d_in[6];
        Wq = (const float*)d_in[7];  bq = (const float*)d_in[8];
        Wk = (const float*)d_in[9];  bk = (const float*)d_in[10];
        Wv = (const float*)d_in[11]; bv = (const float*)d_in[12];
        Wa = (const float*)d_in[13]; ba = (const float*)d_in[14];
        ln1_g = (const float*)d_in[15]; ln1_b = (const float*)d_in[16];
        W1 = (const float*)d_in[17]; b1 = (const float*)d_in[18];
        W2 = (const float*)d_in[19]; b2 = (const float*)d_in[20];
        ln2_g = (const float*)d_in[21]; ln2_b = (const float*)d_in[22];
        in_degrees  = (const int*)d_in[23];
        out_degrees = (const int*)d_in[24];
        spatial_pos = (const int*)d_in[25];
    }

    float *hB, *qB, *kB, *vB, *t1B, *t2B, *nodeB, *biasB;
    cudaGetSymbolAddress((void**)&hB,    g_h);
    cudaGetSymbolAddress((void**)&qB,    g_q);
    cudaGetSymbolAddress((void**)&kB,    g_k);
    cudaGetSymbolAddress((void**)&vB,    g_v);
    cudaGetSymbolAddress((void**)&t1B,   g_t1);
    cudaGetSymbolAddress((void**)&t2B,   g_t2);
    cudaGetSymbolAddress((void**)&nodeB, g_node);
    cudaGetSymbolAddress((void**)&biasB, g_bias);

    float* outp = (float*)d_out;

    // prologue
    node_vec_kernel<<<N_, 256>>>(svd_emb, W_svd, b_svd, in_deg_emb, out_deg_emb,
                                 in_degrees, out_degrees, nodeB);
    add_node_kernel<<<BND / 256, 256>>>(x, nodeB, hB);
    bias_kernel<<<(N_ * N_) / 256, 256>>>(spatial_pos, spatial_emb, biasB);

    dim3 ggrid(B_ * N_ / BM, D_ / BN);       // (64, 4)
    dim3 qkvgrid(B_ * N_ / BM, D_ / BN, 3);  // (64, 4, 3)
    dim3 agrid(N_ / 64, B_ * H_);            // (16, 32) = 512 blocks

    for (int l = 0; l < L_; l++) {
        const float* wq = Wq + (size_t)l * D_ * D_;
        const float* wk = Wk + (size_t)l * D_ * D_;
        const float* wv = Wv + (size_t)l * D_ * D_;
        const float* wa = Wa + (size_t)l * D_ * D_;
        const float* w1 = W1 + (size_t)l * D_ * D_;
        const float* w2 = W2 + (size_t)l * D_ * D_;

        qkv_kernel<<<qkvgrid, 256>>>(hB, wq, wk, wv,
                                     bq + l * D_, bk + l * D_, bv + l * D_,
                                     qB, kB, vB);

        attn_kernel<<<agrid, 64>>>(qB, kB, vB, biasB, t1B);

        gemm256_kernel<<<ggrid, 256>>>(t1B, wa, ba + l * D_, hB, t2B, 0);
        ln_kernel<<<B_ * N_, 256>>>(t2B, ln1_g + l * D_, ln1_b + l * D_, hB);

        gemm256_kernel<<<ggrid, 256>>>(hB, w1, b1 + l * D_, nullptr, t1B, 1);
        gemm256_kernel<<<ggrid, 256>>>(t1B, w2, b2 + l * D_, hB, t2B, 0);

        float* ln2_dst = (l == L_ - 1) ? outp : hB;
        ln_kernel<<<B_ * N_, 256>>>(t2B, ln2_g + l * D_, ln2_b + l * D_, ln2_dst);
    }
}

// round 9
// speedup vs baseline: 1.6607x; 1.6607x over previous
#include <cuda_runtime.h>
#include <math.h>

#define B_ 4
#define N_ 1024
#define H_ 8
#define D_ 256
#define L_ 4
#define DK_ 32
#define NSP_ 512
#define BND (B_*N_*D_)   // 1048576
#define ND  (N_*D_)      // 262144

typedef unsigned long long u64;

// ---------------- f32x2 packed-math helpers (sm_100+) ----------------
__device__ __forceinline__ u64 pk2(float x, float y) {
    u64 r; asm("mov.b64 %0, {%1, %2};" : "=l"(r) : "f"(x), "f"(y)); return r;
}
__device__ __forceinline__ float2 upk2(u64 a) {
    float2 f; asm("mov.b64 {%0, %1}, %2;" : "=f"(f.x), "=f"(f.y) : "l"(a)); return f;
}
__device__ __forceinline__ u64 fma2_(u64 a, u64 b, u64 c) {
    u64 d; asm("fma.rn.f32x2 %0, %1, %2, %3;" : "=l"(d) : "l"(a), "l"(b), "l"(c)); return d;
}
__device__ __forceinline__ u64 mul2_(u64 a, u64 b) {
    u64 d; asm("mul.rn.f32x2 %0, %1, %2;" : "=l"(d) : "l"(a), "l"(b)); return d;
}

// ---------------- scratch (static device globals; no allocation) ----------------
__device__ float g_h [BND];
__device__ float g_q [BND];
__device__ float g_k [BND];
__device__ float g_v [BND];
__device__ float g_t1[BND];
__device__ float g_t2[BND];
__device__ float g_node[ND];
__device__ float g_bias[H_ * N_ * N_];   // 32MB precomputed bias [H][N][N]

// ---------------- prologue: node-level embeddings ----------------
__global__ void node_vec_kernel(const float* __restrict__ svd_emb,
                                const float* __restrict__ W_svd,
                                const float* __restrict__ b_svd,
                                const float* __restrict__ in_deg_emb,
                                const float* __restrict__ out_deg_emb,
                                const int*   __restrict__ in_degrees,
                                const int*   __restrict__ out_degrees,
                                float* __restrict__ nodevec)
{
    int n = blockIdx.x;
    int d = threadIdx.x;           // 256 threads
    __shared__ float pos[32];
    if (d < 32) {
        float v = svd_emb[n * 32 + d];
        pos[d] = (d < 16) ? v : -v;
    }
    __syncthreads();
    int in_i  = in_degrees[n];
    int out_i = out_degrees[n];
    float acc = b_svd[d] + in_deg_emb[in_i * D_ + d] + out_deg_emb[out_i * D_ + d];
#pragma unroll
    for (int k = 0; k < 32; k++)
        acc += pos[k] * W_svd[k * D_ + d];
    nodevec[n * D_ + d] = acc;
}

__global__ void add_node_kernel(const float* __restrict__ x,
                                const float* __restrict__ nodevec,
                                float* __restrict__ h)
{
    int i = blockIdx.x * blockDim.x + threadIdx.x;
    h[i] = x[i] + nodevec[i & (ND - 1)];
}

// ---------------- precompute attention bias ----------------
__global__ void bias_kernel(const int* __restrict__ spatial_pos,
                            const float* __restrict__ spatial_emb,
                            float* __restrict__ bias)
{
    int i = blockIdx.x * 256 + threadIdx.x;     // over N*N = 1M
    int s = spatial_pos[i];
#pragma unroll
    for (int h = 0; h < H_; h++)
        bias[(size_t)h * (N_ * N_) + i] = spatial_emb[s * H_ + h];
}

// ---------------- GEMM: 128x64 tile, 256 threads, 8m x 4n microtile, f32x2 ----------------
#define GBM 128
#define GBN 64
#define GBK 16
__device__ __forceinline__ void gemm_body(const float* __restrict__ A,
                                          const float* __restrict__ W,
                                          const float* __restrict__ bias,
                                          const float* __restrict__ res,
                                          float* __restrict__ out,
                                          int relu, int bm, int bn)
{
    __shared__ __align__(16) float As[GBK][GBM + 4];  // [16][132]
    __shared__ __align__(16) float Bs[GBK][GBN];      // [16][64]

    int tid = threadIdx.x;            // 256
    int tx = tid & 15;                // n dir: 4 cols
    int ty = tid >> 4;                // m dir: 8 rows (4 f32x2 pairs)

    int ar = tid >> 1;                // A row 0..127
    int ac = (tid & 1) * 8;           // A k-chunk 0 or 8
    int br = tid >> 4;                // B k-row 0..15
    int bc = (tid & 15) * 4;          // B n-chunk

    const float* Ap = A + (size_t)(bm + ar) * 256 + ac;
    const float* Wp = W + (size_t)br * 256 + bn + bc;

    float4 a0 = *reinterpret_cast<const float4*>(Ap);
    float4 a1 = *reinterpret_cast<const float4*>(Ap + 4);
    float4 b0 = *reinterpret_cast<const float4*>(Wp);

    u64 acc2[4][4] = {};   // [m-pair p -> rows ty*8+2p,+2p+1][n j]

#pragma unroll 1
    for (int k0 = 0; k0 < 256; k0 += GBK) {
        As[ac + 0][ar] = a0.x; As[ac + 1][ar] = a0.y;
        As[ac + 2][ar] = a0.z; As[ac + 3][ar] = a0.w;
        As[ac + 4][ar] = a1.x; As[ac + 5][ar] = a1.y;
        As[ac + 6][ar] = a1.z; As[ac + 7][ar] = a1.w;
        *reinterpret_cast<float4*>(&Bs[br][bc]) = b0;
        __syncthreads();
        if (k0 + GBK < 256) {
            a0 = *reinterpret_cast<const float4*>(Ap + k0 + GBK);
            a1 = *reinterpret_cast<const float4*>(Ap + k0 + GBK + 4);
            b0 = *reinterpret_cast<const float4*>(Wp + (size_t)(k0 + GBK) * 256);
        }
#pragma unroll
        for (int kk = 0; kk < GBK; kk++) {
            ulonglong2 aA = *reinterpret_cast<const ulonglong2*>(&As[kk][ty * 8]);
            ulonglong2 aB = *reinterpret_cast<const ulonglong2*>(&As[kk][ty * 8 + 4]);
            float4 b4 = *reinterpret_cast<const float4*>(&Bs[kk][tx * 4]);
            u64 bd[4];
            bd[0] = pk2(b4.x, b4.x); bd[1] = pk2(b4.y, b4.y);
            bd[2] = pk2(b4.z, b4.z); bd[3] = pk2(b4.w, b4.w);
            u64 am[4] = {aA.x, aA.y, aB.x, aB.y};
#pragma unroll
            for (int p = 0; p < 4; p++)
#pragma unroll
                for (int j = 0; j < 4; j++)
                    acc2[p][j] = fma2_(am[p], bd[j], acc2[p][j]);
        }
        __syncthreads();
    }

    int n = bn + tx * 4;
    float4 bb = *reinterpret_cast<const float4*>(bias + n);
#pragma unroll
    for (int p = 0; p < 4; p++) {
#pragma unroll
        for (int half = 0; half < 2; half++) {
            int m = bm + ty * 8 + p * 2 + half;
            float4 vv;
            {
                float2 t0 = upk2(acc2[p][0]);
                float2 t1 = upk2(acc2[p][1]);
                float2 t2 = upk2(acc2[p][2]);
                float2 t3 = upk2(acc2[p][3]);
                if (half) { vv.x = t0.y; vv.y = t1.y; vv.z = t2.y; vv.w = t3.y; }
                else      { vv.x = t0.x; vv.y = t1.x; vv.z = t2.x; vv.w = t3.x; }
            }
            vv.x += bb.x; vv.y += bb.y; vv.z += bb.z; vv.w += bb.w;
            if (res) {
                float4 rr = *reinterpret_cast<const float4*>(res + (size_t)m * 256 + n);
                vv.x += rr.x; vv.y += rr.y; vv.z += rr.z; vv.w += rr.w;
            }
            if (relu) {
                vv.x = fmaxf(vv.x, 0.f); vv.y = fmaxf(vv.y, 0.f);
                vv.z = fmaxf(vv.z, 0.f); vv.w = fmaxf(vv.w, 0.f);
            }
            *reinterpret_cast<float4*>(out + (size_t)m * 256 + n) = vv;
        }
    }
}

__global__ void __launch_bounds__(256)
gemm256_kernel(const float* __restrict__ A, const float* __restrict__ W,
               const float* __restrict__ bias, const float* __restrict__ res,
               float* __restrict__ out, int relu)
{
    gemm_body(A, W, bias, res, out, relu, blockIdx.x * GBM, blockIdx.y * GBN);
}

__global__ void __launch_bounds__(256)
qkv_kernel(const float* __restrict__ A,
           const float* __restrict__ Wq, const float* __restrict__ Wk, const float* __restrict__ Wv,
           const float* __restrict__ bq, const float* __restrict__ bk, const float* __restrict__ bv,
           float* __restrict__ q, float* __restrict__ k, float* __restrict__ v)
{
    const float* W; const float* bias; float* out;
    if (blockIdx.z == 0)      { W = Wq; bias = bq; out = q; }
    else if (blockIdx.z == 1) { W = Wk; bias = bk; out = k; }
    else                      { W = Wv; bias = bv; out = v; }
    gemm_body(A, W, bias, nullptr, out, 0, blockIdx.x * GBM, blockIdx.y * GBN);
}

// ---------------- flash attention: lane = query, double-buffered K/V, reg bias ----------------
// grid: (N/128, B*H), block 128. Warp w owns query q0 + w*32 + lane.
__global__ void __launch_bounds__(128)
attn_kernel(const float* __restrict__ q,
            const float* __restrict__ k,
            const float* __restrict__ v,
            const float* __restrict__ bias,   // [H][N][N]
            float* __restrict__ out)
{
    int bh = blockIdx.y;
    int b  = bh >> 3;
    int h  = bh & 7;
    int q0 = blockIdx.x * 128;

    __shared__ __align__(16) float Ks[2][32][36];
    __shared__ __align__(16) float Vs[2][32][36];

    int tid  = threadIdx.x;
    int w    = tid >> 5;
    int lane = tid & 31;
    int qrow = w * 32 + lane;          // 0..127
    int qi   = q0 + qrow;

    // fill indices (fixed per thread)
    int fr0 = tid >> 3;                // 0..15
    int fc0 = (tid & 7) * 4;
    int fr1 = fr0 + 16;                // 16..31

    const float scale = 0.1767766952966369f;   // 1/sqrt(32)

    u64 qv2[16], o2[16];
    {
        const float4* qp = reinterpret_cast<const float4*>(
            q + ((size_t)(b * N_ + qi)) * D_ + h * DK_);
#pragma unroll
        for (int d4 = 0; d4 < 8; d4++) {
            float4 t = qp[d4];
            qv2[d4*2+0] = pk2(t.x * scale, t.y * scale);
            qv2[d4*2+1] = pk2(t.z * scale, t.w * scale);
        }
    }
#pragma unroll
    for (int d = 0; d < 16; d++) o2[d] = 0ull;
    float m = -1e30f, l = 0.0f;

    const float* kvbase = (const float*)0;
    const float* brow = bias + (size_t)h * (N_ * N_) + (size_t)qi * N_;

    float4 kf0, kf1, vf0, vf1, bf[8];

    // prefetch tile 0
    {
        const float* kb = k + ((size_t)(b * N_)) * D_ + h * DK_;
        const float* vb = v + ((size_t)(b * N_)) * D_ + h * DK_;
        kf0 = *reinterpret_cast<const float4*>(kb + (size_t)fr0 * D_ + fc0);
        kf1 = *reinterpret_cast<const float4*>(kb + (size_t)fr1 * D_ + fc0);
        vf0 = *reinterpret_cast<const float4*>(vb + (size_t)fr0 * D_ + fc0);
        vf1 = *reinterpret_cast<const float4*>(vb + (size_t)fr1 * D_ + fc0);
#pragma unroll
        for (int j = 0; j < 8; j++)
            bf[j] = *reinterpret_cast<const float4*>(brow + j * 4);
        *reinterpret_cast<float4*>(&Ks[0][fr0][fc0]) = kf0;
        *reinterpret_cast<float4*>(&Ks[0][fr1][fc0]) = kf1;
        *reinterpret_cast<float4*>(&Vs[0][fr0][fc0]) = vf0;
        *reinterpret_cast<float4*>(&Vs[0][fr1][fc0]) = vf1;
    }
    __syncthreads();

#pragma unroll 1
    for (int t = 0; t < 32; t++) {
        int cur = t & 1;
        int k0n = (t + 1) * 32;

        // consume bias prefetch into score init
        float s[32];
#pragma unroll
        for (int j = 0; j < 8; j++) {
            s[j*4+0] = bf[j].x; s[j*4+1] = bf[j].y;
            s[j*4+2] = bf[j].z; s[j*4+3] = bf[j].w;
        }

        // prefetch next tile (LDG latency hidden by compute below)
        if (t < 31) {
            const float* kb = k + ((size_t)(b * N_ + k0n)) * D_ + h * DK_;
            const float* vb = v + ((size_t)(b * N_ + k0n)) * D_ + h * DK_;
            kf0 = *reinterpret_cast<const float4*>(kb + (size_t)fr0 * D_ + fc0);
            kf1 = *reinterpret_cast<const float4*>(kb + (size_t)fr1 * D_ + fc0);
            vf0 = *reinterpret_cast<const float4*>(vb + (size_t)fr0 * D_ + fc0);
            vf1 = *reinterpret_cast<const float4*>(vb + (size_t)fr1 * D_ + fc0);
#pragma unroll
            for (int j = 0; j < 8; j++)
                bf[j] = *reinterpret_cast<const float4*>(brow + k0n + j * 4);
        }

        // scores: dual f32x2 chains per key
#pragma unroll
        for (int kk = 0; kk < 32; kk++) {
            u64 svA = 0ull, svB = 0ull;
            const ulonglong2* kr = reinterpret_cast<const ulonglong2*>(&Ks[cur][kk][0]);
#pragma unroll
            for (int p = 0; p < 8; p++) {
                ulonglong2 kp = kr[p];
                svA = fma2_(qv2[2*p + 0], kp.x, svA);
                svB = fma2_(qv2[2*p + 1], kp.y, svB);
            }
            float2 sa = upk2(svA);
            float2 sb = upk2(svB);
            s[kk] += (sa.x + sa.y) + (sb.x + sb.y);
        }

        float tmax = s[0];
#pragma unroll
        for (int kk = 1; kk < 32; kk++) tmax = fmaxf(tmax, s[kk]);
        float mnew  = fmaxf(m, tmax);
        float alpha = __expf(m - mnew);
        float psum = 0.0f;
#pragma unroll
        for (int kk = 0; kk < 32; kk++) {
            float p = __expf(s[kk] - mnew);
            s[kk] = p;
            psum += p;
        }
        l = l * alpha + psum;
        m = mnew;

        u64 al2 = pk2(alpha, alpha);
#pragma unroll
        for (int d = 0; d < 16; d++) o2[d] = mul2_(o2[d], al2);

#pragma unroll
        for (int kk = 0; kk < 32; kk++) {
            u64 p2 = pk2(s[kk], s[kk]);
            const ulonglong2* vr = reinterpret_cast<const ulonglong2*>(&Vs[cur][kk][0]);
#pragma unroll
            for (int p = 0; p < 8; p++) {
                ulonglong2 vp = vr[p];
                o2[2*p + 0] = fma2_(p2, vp.x, o2[2*p + 0]);
                o2[2*p + 1] = fma2_(p2, vp.y, o2[2*p + 1]);
            }
        }

        // stage next tile into the other buffer (safe: everyone is past it)
        if (t < 31) {
            int nxt = 1 - cur;
            *reinterpret_cast<float4*>(&Ks[nxt][fr0][fc0]) = kf0;
            *reinterpret_cast<float4*>(&Ks[nxt][fr1][fc0]) = kf1;
            *reinterpret_cast<float4*>(&Vs[nxt][fr0][fc0]) = vf0;
            *reinterpret_cast<float4*>(&Vs[nxt][fr1][fc0]) = vf1;
        }
        __syncthreads();
    }
    (void)kvbase;

    float inv = 1.0f / l;
    float* ob = out + ((size_t)(b * N_ + qi)) * D_ + h * DK_;
#pragma unroll
    for (int d4 = 0; d4 < 8; d4++) {
        float2 t0 = upk2(o2[d4*2 + 0]);
        float2 t1 = upk2(o2[d4*2 + 1]);
        float4 t;
        t.x = t0.x * inv; t.y = t0.y * inv;
        t.z = t1.x * inv; t.w = t1.y * inv;
        *reinterpret_cast<float4*>(ob + d4 * 4) = t;
    }
}

// ---------------- LayerNorm over D=256 ----------------
__global__ void __launch_bounds__(256)
ln_kernel(const float* __restrict__ z,
          const float* __restrict__ g,
          const float* __restrict__ bta,
          float* __restrict__ out)
{
    int row = blockIdx.x;
    int t   = threadIdx.x;
    int lane = t & 31, wid = t >> 5;
    __shared__ float red1[8], red2[8];

    float vv = z[(size_t)row * 256 + t];
    float s = vv;
#pragma unroll
    for (int off = 16; off; off >>= 1) s += __shfl_xor_sync(0xffffffffu, s, off);
    if (lane == 0) red1[wid] = s;
    __syncthreads();
    float tot = 0.0f;
#pragma unroll
    for (int i = 0; i < 8; i++) tot += red1[i];
    float mu = tot * (1.0f / 256.0f);

    float d = vv - mu;
    float sq = d * d;
#pragma unroll
    for (int off = 16; off; off >>= 1) sq += __shfl_xor_sync(0xffffffffu, sq, off);
    if (lane == 0) red2[wid] = sq;
    __syncthreads();
    float var = 0.0f;
#pragma unroll
    for (int i = 0; i < 8; i++) var += red2[i];
    var *= (1.0f / 256.0f);

    out[(size_t)row * 256 + t] = d * rsqrtf(var + 1e-6f) * g[t] + bta[t];
}

// ---------------- launch ----------------
extern "C" void kernel_launch(void* const* d_in, const int* in_sizes, int n_in,
                              void* d_out, int out_size)
{
    (void)n_in; (void)out_size;

    const float *x, *svd_emb, *W_svd, *b_svd, *in_deg_emb, *out_deg_emb, *spatial_emb;
    const float *Wq, *Wk, *Wv, *Wa, *W1, *W2;
    const float *bq, *bk, *bv, *ba, *b1, *b2;
    const float *ln1_g, *ln1_b, *ln2_g, *ln2_b;
    const int *in_degrees, *out_degrees, *spatial_pos;

    if (in_sizes[1] == 1024) {
        // setup_inputs dict order
        x           = (const float*)d_in[0];
        in_degrees  = (const int*)  d_in[1];
        out_degrees = (const int*)  d_in[2];
        spatial_pos = (const int*)  d_in[3];
        svd_emb     = (const float*)d_in[4];
        in_deg_emb  = (const float*)d_in[5];
        out_deg_emb = (const float*)d_in[6];
        spatial_emb = (const float*)d_in[7];
        W_svd       = (const float*)d_in[8];
        b_svd       = (const float*)d_in[9];
        Wq = (const float*)d_in[10]; Wk = (const float*)d_in[11];
        Wv = (const float*)d_in[12]; Wa = (const float*)d_in[13];
        W1 = (const float*)d_in[14]; W2 = (const float*)d_in[15];
        bq = (const float*)d_in[16]; bk = (const float*)d_in[17];
        bv = (const float*)d_in[18]; ba = (const float*)d_in[19];
        b1 = (const float*)d_in[20]; b2 = (const float*)d_in[21];
        ln1_b = (const float*)d_in[22]; ln2_b = (const float*)d_in[23];
        ln1_g = (const float*)d_in[24]; ln2_g = (const float*)d_in[25];
    } else {
        // reference() signature order
        x           = (const float*)d_in[0];
        svd_emb     = (const float*)d_in[1];
        W_svd       = (const float*)d_in[2];
        b_svd       = (const float*)d_in[3];
        in_deg_emb  = (const float*)d_in[4];
        out_deg_emb = (const float*)d_in[5];
        spatial_emb = (const float*)d_in[6];
        Wq = (const float*)d_in[7];  bq = (const float*)d_in[8];
        Wk = (const float*)d_in[9];  bk = (const float*)d_in[10];
        Wv = (const float*)d_in[11]; bv = (const float*)d_in[12];
        Wa = (const float*)d_in[13]; ba = (const float*)d_in[14];
        ln1_g = (const float*)d_in[15]; ln1_b = (const float*)d_in[16];
        W1 = (const float*)d_in[17]; b1 = (const float*)d_in[18];
        W2 = (const float*)d_in[19]; b2 = (const float*)d_in[20];
        ln2_g = (const float*)d_in[21]; ln2_b = (const float*)d_in[22];
        in_degrees  = (const int*)d_in[23];
        out_degrees = (const int*)d_in[24];
        spatial_pos = (const int*)d_in[25];
    }

    float *hB, *qB, *kB, *vB, *t1B, *t2B, *nodeB, *biasB;
    cudaGetSymbolAddress((void**)&hB,    g_h);
    cudaGetSymbolAddress((void**)&qB,    g_q);
    cudaGetSymbolAddress((void**)&kB,    g_k);
    cudaGetSymbolAddress((void**)&vB,    g_v);
    cudaGetSymbolAddress((void**)&t1B,   g_t1);
    cudaGetSymbolAddress((void**)&t2B,   g_t2);
    cudaGetSymbolAddress((void**)&nodeB, g_node);
    cudaGetSymbolAddress((void**)&biasB, g_bias);

    float* outp = (float*)d_out;

    // prologue
    node_vec_kernel<<<N_, 256>>>(svd_emb, W_svd, b_svd, in_deg_emb, out_deg_emb,
                                 in_degrees, out_degrees, nodeB);
    add_node_kernel<<<BND / 256, 256>>>(x, nodeB, hB);
    bias_kernel<<<(N_ * N_) / 256, 256>>>(spatial_pos, spatial_emb, biasB);

    dim3 ggrid(B_ * N_ / GBM, D_ / GBN);       // (32, 4)
    dim3 qkvgrid(B_ * N_ / GBM, D_ / GBN, 3);  // (32, 4, 3)
    dim3 agrid(N_ / 128, B_ * H_);             // (8, 32)

    for (int l = 0; l < L_; l++) {
        const float* wq = Wq + (size_t)l * D_ * D_;
        const float* wk = Wk + (size_t)l * D_ * D_;
        const float* wv = Wv + (size_t)l * D_ * D_;
        const float* wa = Wa + (size_t)l * D_ * D_;
        const float* w1 = W1 + (size_t)l * D_ * D_;
        const float* w2 = W2 + (size_t)l * D_ * D_;

        qkv_kernel<<<qkvgrid, 256>>>(hB, wq, wk, wv,
                                     bq + l * D_, bk + l * D_, bv + l * D_,
                                     qB, kB, vB);

        attn_kernel<<<agrid, 128>>>(qB, kB, vB, biasB, t1B);

        gemm256_kernel<<<ggrid, 256>>>(t1B, wa, ba + l * D_, hB, t2B, 0);
        ln_kernel<<<B_ * N_, 256>>>(t2B, ln1_g + l * D_, ln1_b + l * D_, hB);

        gemm256_kernel<<<ggrid, 256>>>(hB, w1, b1 + l * D_, nullptr, t1B, 1);
        gemm256_kernel<<<ggrid, 256>>>(t1B, w2, b2 + l * D_, hB, t2B, 0);

        float* ln2_dst = (l == L_ - 1) ? outp : hB;
        ln_kernel<<<B_ * N_, 256>>>(t2B, ln2_g + l * D_, ln2_b + l * D_, ln2_dst);
    }
}